// round 1
// baseline (speedup 1.0000x reference)
#include <cuda_runtime.h>

// FeatureContraction: out[b,c,w,x,v] = sum_i x[b,c,w,x,v,i] * attr[b,c,i]
// B=128, C=128, X=3, Y=16  -> x: [16384, 768, 16] f32 (flattened),
//                             attr: [16384, 16], out: [16384, 768]
// Pure HBM-streaming problem (~855 MB traffic). One block per (b,c).

#define BC_TOTAL 16384      // B*C
#define WXV      768        // X*Y*Y = 3*16*16
#define THREADS  256
#define PER_THR  (WXV / THREADS)   // 3

__global__ __launch_bounds__(THREADS)
void feature_contraction_kernel(const float4* __restrict__ x,
                                const float4* __restrict__ attr,
                                float* __restrict__ out)
{
    const int bc = blockIdx.x;

    // Stage attr[bc, 0:16] through shared memory, then broadcast to registers.
    __shared__ float4 s_a[4];
    if (threadIdx.x < 4) {
        s_a[threadIdx.x] = attr[(size_t)bc * 4 + threadIdx.x];
    }
    __syncthreads();

    const float4 a0 = s_a[0];
    const float4 a1 = s_a[1];
    const float4 a2 = s_a[2];
    const float4 a3 = s_a[3];

    // x base for this (b,c): WXV output elems * 4 float4 each
    const float4* __restrict__ xb = x + (size_t)bc * WXV * 4;
    float* __restrict__ ob = out + (size_t)bc * WXV;

    // Each thread handles PER_THR output elements. Front-batch all loads
    // (12 independent LDG.128) so MLP covers DRAM latency.
    float4 v[PER_THR][4];
    int    o[PER_THR];

#pragma unroll
    for (int k = 0; k < PER_THR; k++) {
        o[k] = k * THREADS + threadIdx.x;
        const float4* __restrict__ xp = xb + (size_t)o[k] * 4;
        v[k][0] = xp[0];
        v[k][1] = xp[1];
        v[k][2] = xp[2];
        v[k][3] = xp[3];
    }

#pragma unroll
    for (int k = 0; k < PER_THR; k++) {
        float s;
        s  = v[k][0].x * a0.x;
        s += v[k][0].y * a0.y;
        s += v[k][0].z * a0.z;
        s += v[k][0].w * a0.w;
        s += v[k][1].x * a1.x;
        s += v[k][1].y * a1.y;
        s += v[k][1].z * a1.z;
        s += v[k][1].w * a1.w;
        s += v[k][2].x * a2.x;
        s += v[k][2].y * a2.y;
        s += v[k][2].z * a2.z;
        s += v[k][2].w * a2.w;
        s += v[k][3].x * a3.x;
        s += v[k][3].y * a3.y;
        s += v[k][3].z * a3.z;
        s += v[k][3].w * a3.w;
        ob[o[k]] = s;
    }
}

extern "C" void kernel_launch(void* const* d_in, const int* in_sizes, int n_in,
                              void* d_out, int out_size)
{
    const float4* x    = (const float4*)d_in[0];   // [16384, 768, 16] f32
    const float4* attr = (const float4*)d_in[1];   // [16384, 16] f32
    float*        out  = (float*)d_out;            // [16384, 768] f32

    feature_contraction_kernel<<<BC_TOTAL, THREADS>>>(x, attr, out);
}